// round 1
// baseline (speedup 1.0000x reference)
#include <cuda_runtime.h>
#include <cuda_bf16.h>
#include <math.h>

// ---------------- problem constants (max sizes for static scratch) ----------
#define MAXN 50000
#define MAXE 800000
#define MAXNE 100000
#define D 128

// ---------------- device scratch (allocation-free rule) ---------------------
__device__ float g_bufA[(size_t)MAXN * D];
__device__ float g_bufB[(size_t)MAXN * D];
__device__ float g_Z [(size_t)MAXNE * D];
__device__ float g_Z2[(size_t)MAXNE * D];
__device__ int   g_deg[MAXN];
__device__ int   g_rowptr[MAXN + 1];
__device__ int   g_cur[MAXN];
__device__ int   g_eidx[MAXE];

// ---------------- small utility kernels -------------------------------------
__global__ void zero_int_kernel(int* p, int n) {
    for (int i = blockIdx.x * blockDim.x + threadIdx.x; i < n; i += gridDim.x * blockDim.x)
        p[i] = 0;
}

__global__ void hist_kernel(const int* __restrict__ dst, int E, int* __restrict__ deg) {
    for (int e = blockIdx.x * blockDim.x + threadIdx.x; e < E; e += gridDim.x * blockDim.x)
        atomicAdd(&deg[dst[e]], 1);
}

// single-block exclusive scan over deg[n] -> rowptr / cur
__global__ void scan_kernel(const int* __restrict__ deg, int* __restrict__ rowptr,
                            int* __restrict__ cur, int n) {
    __shared__ int s[1024];
    __shared__ int carry_s;
    int tid = threadIdx.x;
    if (tid == 0) carry_s = 0;
    __syncthreads();
    for (int base = 0; base < n; base += 1024) {
        int i = base + tid;
        int v = (i < n) ? deg[i] : 0;
        s[tid] = v;
        __syncthreads();
        #pragma unroll
        for (int off = 1; off < 1024; off <<= 1) {
            int t = (tid >= off) ? s[tid - off] : 0;
            __syncthreads();
            s[tid] += t;
            __syncthreads();
        }
        int inc = s[tid];
        int excl = carry_s + inc - v;     // read carry before update
        if (i < n) { rowptr[i] = excl; cur[i] = excl; }
        __syncthreads();
        if (tid == 1023) carry_s += s[1023];
        __syncthreads();
    }
    if (tid == 0) rowptr[n] = carry_s;
}

__global__ void fill_csr_kernel(const int* __restrict__ src, const int* __restrict__ dst,
                                int E, int* __restrict__ cur, int* __restrict__ eidx) {
    for (int e = blockIdx.x * blockDim.x + threadIdx.x; e < E; e += gridDim.x * blockDim.x) {
        int d = dst[e];
        int p = atomicAdd(&cur[d], 1);
        eidx[p] = src[e];
    }
}

// ---------------- aggregation: out[d] = sum_{src in CSR[d]} H[src] (+bias, relu) ----
__global__ void agg_kernel(const float* __restrict__ H, const int* __restrict__ rowptr,
                           const int* __restrict__ eidx, const float* __restrict__ bias,
                           float* __restrict__ out, int relu) {
    int d = blockIdx.x;
    int c = threadIdx.x;                  // 128 threads = 128 columns
    __shared__ int nb[128];
    int beg = rowptr[d], end = rowptr[d + 1];
    float acc = 0.0f;
    for (int j0 = beg; j0 < end; j0 += 128) {
        int cnt = min(128, end - j0);
        __syncthreads();
        if (c < cnt) nb[c] = eidx[j0 + c];
        __syncthreads();
        for (int j = 0; j < cnt; j++)
            acc += H[(size_t)nb[j] * D + c];
    }
    float v = acc + bias[c];
    if (relu) v = fmaxf(v, 0.0f);
    out[(size_t)d * D + c] = v;
}

// ---------------- GEMM: C[M,128] = A[M,128] @ W[128,128] (+bias)(+relu) -----
// 256 threads, BM=BN=128, BK=16, each thread 8x8.
#define WROW 144                           // padded Ws row stride (floats)
#define WS_FLOATS (128 * WROW)             // 18432
#define AS_STRIDE 136
#define AS_FLOATS (16 * AS_STRIDE)         // 2176
#define GEMM_SMEM_BYTES ((WS_FLOATS + AS_FLOATS) * 4)

__global__ void __launch_bounds__(256)
gemm128_kernel(const float* __restrict__ A, const float* __restrict__ W,
               const float* __restrict__ bias, float* __restrict__ C,
               int M, int relu) {
    extern __shared__ float smem[];
    float* Ws = smem;                      // padded [128][WROW]
    float* As = smem + WS_FLOATS;          // transposed [16][AS_STRIDE] (k-major)

    int tid = threadIdx.x;
    // load full W with +4-floats-per-32 pad: c' = c + (c>>5)*4
    const float4* Wv = (const float4*)W;
    for (int i4 = tid; i4 < 4096; i4 += 256) {
        int k = i4 >> 5;
        int c = (i4 & 31) << 2;
        float4 v = Wv[i4];
        *(float4*)&Ws[k * WROW + c + ((c >> 5) << 2)] = v;
    }

    int rowBase = blockIdx.x * 128;
    int tr = tid >> 4;                     // 0..15
    int tc = tid & 15;                     // 0..15
    int row0 = tr * 8;
    int col0 = tc * 8;
    int woff = col0 + ((col0 >> 5) << 2);

    float acc[8][8];
    #pragma unroll
    for (int i = 0; i < 8; i++)
        #pragma unroll
        for (int j = 0; j < 8; j++) acc[i][j] = 0.0f;

    __syncthreads();

    for (int k0 = 0; k0 < 128; k0 += 16) {
        __syncthreads();
        // stage A tile [128 x 16], transposed into As[k][m]
        #pragma unroll
        for (int p = 0; p < 2; p++) {
            int t = tid + p * 256;
            int ar = t >> 2;               // 0..127
            int ac4 = (t & 3) << 2;        // 0,4,8,12
            int grow = rowBase + ar;
            float4 v = (grow < M) ? *(const float4*)(A + (size_t)grow * D + k0 + ac4)
                                  : make_float4(0.f, 0.f, 0.f, 0.f);
            As[(ac4 + 0) * AS_STRIDE + ar] = v.x;
            As[(ac4 + 1) * AS_STRIDE + ar] = v.y;
            As[(ac4 + 2) * AS_STRIDE + ar] = v.z;
            As[(ac4 + 3) * AS_STRIDE + ar] = v.w;
        }
        __syncthreads();
        #pragma unroll
        for (int kk = 0; kk < 16; kk++) {
            float4 a0 = *(const float4*)&As[kk * AS_STRIDE + row0];
            float4 a1 = *(const float4*)&As[kk * AS_STRIDE + row0 + 4];
            const float* wp = &Ws[(k0 + kk) * WROW + woff];
            float4 w0 = *(const float4*)wp;
            float4 w1 = *(const float4*)(wp + 4);
            float a[8] = {a0.x, a0.y, a0.z, a0.w, a1.x, a1.y, a1.z, a1.w};
            float w[8] = {w0.x, w0.y, w0.z, w0.w, w1.x, w1.y, w1.z, w1.w};
            #pragma unroll
            for (int i = 0; i < 8; i++)
                #pragma unroll
                for (int j = 0; j < 8; j++)
                    acc[i][j] = fmaf(a[i], w[j], acc[i][j]);
        }
    }

    // epilogue
    float bv[8];
    #pragma unroll
    for (int j = 0; j < 8; j++) bv[j] = bias ? bias[col0 + j] : 0.0f;
    #pragma unroll
    for (int i = 0; i < 8; i++) {
        int gr = rowBase + row0 + i;
        if (gr >= M) break;
        float o[8];
        #pragma unroll
        for (int j = 0; j < 8; j++) {
            float v = acc[i][j] + bv[j];
            o[j] = relu ? fmaxf(v, 0.0f) : v;
        }
        float* cp = C + (size_t)gr * D + col0;
        *(float4*)cp       = make_float4(o[0], o[1], o[2], o[3]);
        *(float4*)(cp + 4) = make_float4(o[4], o[5], o[6], o[7]);
    }
}

// ---------------- Z[q] = emb[src_q] * emb[dst_q] (elementwise, float4) -------
__global__ void zbuild_kernel(const float* __restrict__ emb, const int* __restrict__ tedges,
                              float* __restrict__ Z, int NE) {
    int n4 = NE * 32;
    for (int idx = blockIdx.x * blockDim.x + threadIdx.x; idx < n4; idx += gridDim.x * blockDim.x) {
        int q = idx >> 5;
        int c4 = idx & 31;
        int s = tedges[2 * q];
        int d = tedges[2 * q + 1];
        float4 a = *(const float4*)(emb + (size_t)s * D + c4 * 4);
        float4 b = *(const float4*)(emb + (size_t)d * D + c4 * 4);
        ((float4*)Z)[idx] = make_float4(a.x * b.x, a.y * b.y, a.z * b.z, a.w * b.w);
    }
}

// ---------------- final: z@P3+pb3, L2-normalize, log_softmax -----------------
__global__ void final_kernel(const float* __restrict__ Zin, const float* __restrict__ P3,
                             const float* __restrict__ pb3, float* __restrict__ out, int NE) {
    int gw = (blockIdx.x * blockDim.x + threadIdx.x) >> 5;
    int lane = threadIdx.x & 31;
    if (gw >= NE) return;
    float4 v = ((const float4*)(Zin + (size_t)gw * D))[lane];
    int k = lane * 4;
    // P3 is [128][2] row-major
    float p0 = v.x * P3[2 * k] + v.y * P3[2 * (k + 1)] + v.z * P3[2 * (k + 2)] + v.w * P3[2 * (k + 3)];
    float p1 = v.x * P3[2 * k + 1] + v.y * P3[2 * (k + 1) + 1] + v.z * P3[2 * (k + 2) + 1] + v.w * P3[2 * (k + 3) + 1];
    #pragma unroll
    for (int off = 16; off > 0; off >>= 1) {
        p0 += __shfl_xor_sync(0xFFFFFFFFu, p0, off);
        p1 += __shfl_xor_sync(0xFFFFFFFFu, p1, off);
    }
    if (lane == 0) {
        float z0 = p0 + pb3[0];
        float z1 = p1 + pb3[1];
        float nrm = fmaxf(sqrtf(z0 * z0 + z1 * z1), 1e-12f);
        z0 /= nrm; z1 /= nrm;
        float m = fmaxf(z0, z1);
        float lse = m + logf(expf(z0 - m) + expf(z1 - m));
        out[2 * gw]     = z0 - lse;
        out[2 * gw + 1] = z1 - lse;
    }
}

// ---------------- launch ------------------------------------------------------
extern "C" void kernel_launch(void* const* d_in, const int* in_sizes, int n_in,
                              void* d_out, int out_size) {
    const float* x    = (const float*)d_in[0];
    const int*   adj  = (const int*)d_in[1];   // [2,E]: src=[0,E), dst=[E,2E)
    const int*   tedg = (const int*)d_in[2];   // [NE,2] interleaved
    const float* W1 = (const float*)d_in[3];  const float* b1  = (const float*)d_in[4];
    const float* W2 = (const float*)d_in[5];  const float* b2  = (const float*)d_in[6];
    const float* W3 = (const float*)d_in[7];  const float* b3  = (const float*)d_in[8];
    const float* P1 = (const float*)d_in[9];  const float* pb1 = (const float*)d_in[10];
    const float* P2 = (const float*)d_in[11]; const float* pb2 = (const float*)d_in[12];
    const float* P3 = (const float*)d_in[13]; const float* pb3 = (const float*)d_in[14];
    float* out = (float*)d_out;

    int N  = in_sizes[0] / D;
    int E  = in_sizes[1] / 2;
    int NE = in_sizes[2] / 2;

    cudaFuncSetAttribute((const void*)gemm128_kernel,
                         cudaFuncAttributeMaxDynamicSharedMemorySize, GEMM_SMEM_BYTES);

    float *bufA, *bufB, *Z, *Z2;
    int *deg, *rowptr, *cur, *eidx;
    cudaGetSymbolAddress((void**)&bufA, g_bufA);
    cudaGetSymbolAddress((void**)&bufB, g_bufB);
    cudaGetSymbolAddress((void**)&Z,    g_Z);
    cudaGetSymbolAddress((void**)&Z2,   g_Z2);
    cudaGetSymbolAddress((void**)&deg,    g_deg);
    cudaGetSymbolAddress((void**)&rowptr, g_rowptr);
    cudaGetSymbolAddress((void**)&cur,    g_cur);
    cudaGetSymbolAddress((void**)&eidx,   g_eidx);

    const int* src = adj;
    const int* dst = adj + E;

    // ---- CSR build (by dst) ----
    zero_int_kernel<<<(N + 255) / 256, 256>>>(deg, N);
    hist_kernel<<<(E + 255) / 256, 256>>>(dst, E, deg);
    scan_kernel<<<1, 1024>>>(deg, rowptr, cur, N);
    fill_csr_kernel<<<(E + 255) / 256, 256>>>(src, dst, E, cur, eidx);

    int gblkN  = (N + 127) / 128;
    int gblkNE = (NE + 127) / 128;

    // ---- GCN trunk ----
    gemm128_kernel<<<gblkN, 256, GEMM_SMEM_BYTES>>>(x, W1, nullptr, bufA, N, 0);
    agg_kernel<<<N, 128>>>(bufA, rowptr, eidx, b1, bufB, 1);
    gemm128_kernel<<<gblkN, 256, GEMM_SMEM_BYTES>>>(bufB, W2, nullptr, bufA, N, 0);
    agg_kernel<<<N, 128>>>(bufA, rowptr, eidx, b2, bufB, 1);
    gemm128_kernel<<<gblkN, 256, GEMM_SMEM_BYTES>>>(bufB, W3, nullptr, bufA, N, 0);
    agg_kernel<<<N, 128>>>(bufA, rowptr, eidx, b3, bufB, 0);   // emb -> bufB

    // ---- link predictor ----
    zbuild_kernel<<<(NE * 32 + 255) / 256, 256>>>(bufB, tedg, Z, NE);
    gemm128_kernel<<<gblkNE, 256, GEMM_SMEM_BYTES>>>(Z,  P1, pb1, Z2, NE, 1);
    gemm128_kernel<<<gblkNE, 256, GEMM_SMEM_BYTES>>>(Z2, P2, pb2, Z,  NE, 1);
    final_kernel<<<(NE * 32 + 255) / 256, 256>>>(Z, P3, pb3, out, NE);
}

// round 3
// speedup vs baseline: 1.6169x; 1.6169x over previous
#include <cuda_runtime.h>
#include <cuda_bf16.h>
#include <math.h>
#include <stdint.h>

// ---------------- problem constants ----------------
#define MAXN 50000
#define MAXE 800000
#define MAXNE 100000
#define D 128

// ---------------- device scratch ----------------
__device__ float g_bufA[(size_t)MAXN * D];
__device__ float g_bufB[(size_t)MAXN * D];
__device__ float g_Z [(size_t)MAXNE * D];
__device__ float g_Z2[(size_t)MAXNE * D];
__device__ int   g_deg[MAXN];
__device__ int   g_rowptr[MAXN + 1];
__device__ int   g_cur[MAXN];
__device__ int   g_eidx[MAXE];
// pre-transposed bf16 weights Wt[n][k] (5 x 128x128), hi & lo halves
__device__ __nv_bfloat16 g_Whi[5 * 16384];
__device__ __nv_bfloat16 g_Wlo[5 * 16384];

// ---------------- PTX helpers ----------------
__device__ __forceinline__ uint32_t smem_u32(const void* p) {
    uint32_t a;
    asm("{ .reg .u64 t; cvta.to.shared.u64 t, %1; cvt.u32.u64 %0, t; }" : "=r"(a) : "l"(p));
    return a;
}
__device__ __forceinline__ void ldsm4(uint32_t* r, uint32_t addr) {
    asm volatile("ldmatrix.sync.aligned.m8n8.x4.shared.b16 {%0,%1,%2,%3}, [%4];"
        : "=r"(r[0]), "=r"(r[1]), "=r"(r[2]), "=r"(r[3]) : "r"(addr));
}
__device__ __forceinline__ void mma16816(float* c, const uint32_t* a, const uint32_t* b) {
    asm volatile(
        "mma.sync.aligned.m16n8k16.row.col.f32.bf16.bf16.f32 "
        "{%0,%1,%2,%3}, {%4,%5,%6,%7}, {%8,%9}, {%0,%1,%2,%3};"
        : "+f"(c[0]), "+f"(c[1]), "+f"(c[2]), "+f"(c[3])
        : "r"(a[0]), "r"(a[1]), "r"(a[2]), "r"(a[3]), "r"(b[0]), "r"(b[1]));
}

// ---------------- CSR build kernels ----------------
__global__ void zero_int_kernel(int* p, int n) {
    for (int i = blockIdx.x * blockDim.x + threadIdx.x; i < n; i += gridDim.x * blockDim.x)
        p[i] = 0;
}
__global__ void hist_kernel(const int* __restrict__ dst, int E, int* __restrict__ deg) {
    for (int e = blockIdx.x * blockDim.x + threadIdx.x; e < E; e += gridDim.x * blockDim.x)
        atomicAdd(&deg[dst[e]], 1);
}
// single-block exclusive scan (warp-shuffle based)
__global__ void scan_kernel(const int* __restrict__ deg, int* __restrict__ rowptr,
                            int* __restrict__ cur, int n) {
    __shared__ int wsum[32];
    __shared__ int carry_s;
    int tid = threadIdx.x, lane = tid & 31, w = tid >> 5;
    if (tid == 0) carry_s = 0;
    __syncthreads();
    for (int base = 0; base < n; base += 1024) {
        int i = base + tid;
        int v = (i < n) ? deg[i] : 0;
        int s = v;
        #pragma unroll
        for (int off = 1; off < 32; off <<= 1) {
            int t = __shfl_up_sync(0xFFFFFFFFu, s, off);
            if (lane >= off) s += t;
        }
        if (lane == 31) wsum[w] = s;
        __syncthreads();
        if (w == 0) {
            int ws = wsum[lane];
            #pragma unroll
            for (int off = 1; off < 32; off <<= 1) {
                int t = __shfl_up_sync(0xFFFFFFFFu, ws, off);
                if (lane >= off) ws += t;
            }
            wsum[lane] = ws;
        }
        __syncthreads();
        int prev = (w > 0) ? wsum[w - 1] : 0;
        int excl = carry_s + prev + s - v;
        if (i < n) { rowptr[i] = excl; cur[i] = excl; }
        __syncthreads();
        if (tid == 1023) carry_s += wsum[31];
        __syncthreads();
    }
    if (threadIdx.x == 0) rowptr[n] = carry_s;
}
__global__ void fill_csr_kernel(const int* __restrict__ src, const int* __restrict__ dst,
                                int E, int* __restrict__ cur, int* __restrict__ eidx) {
    for (int e = blockIdx.x * blockDim.x + threadIdx.x; e < E; e += gridDim.x * blockDim.x) {
        int d = dst[e];
        int p = atomicAdd(&cur[d], 1);
        eidx[p] = src[e];
    }
}

// ---------------- weight prep: W[k][n] fp32 -> Wt[n][k] bf16 hi/lo ----------------
__global__ void prep_weights_kernel(const float* W1, const float* W2, const float* W3,
                                    const float* P1, const float* P2,
                                    __nv_bfloat16* hi, __nv_bfloat16* lo) {
    int idx = blockIdx.x * blockDim.x + threadIdx.x;
    if (idx >= 5 * 16384) return;
    int w = idx >> 14;
    int t = idx & 16383;
    int n = t >> 7;
    int k = t & 127;
    const float* Ws = (w == 0) ? W1 : (w == 1) ? W2 : (w == 2) ? W3 : (w == 3) ? P1 : P2;
    float v = Ws[(k << 7) | n];
    __nv_bfloat16 h = __float2bfloat16(v);
    float rem = v - __bfloat162float(h);
    __nv_bfloat16 l = __float2bfloat16(rem);
    hi[idx] = h;
    lo[idx] = l;
}

// ---------------- mma.sync GEMM: C[M,128] = A[M,128] @ W[128,128] (+bias)(+relu) ----
// 256 threads = 8 warps (4x2). Warp tile 32x64. bf16 hi/lo 3-pass.
#define ASTRIDE 136                       // padded row stride (bf16 elems)
#define S_AHI 0
#define S_ALO (128 * ASTRIDE)             // 17408
#define S_WHI (2 * 128 * ASTRIDE)
#define S_WLO (3 * 128 * ASTRIDE)
#define SMEM_ELEMS (4 * 128 * ASTRIDE)    // 69632 bf16
#define SMEM_BYTES (SMEM_ELEMS * 2)       // 139264 B

__global__ void __launch_bounds__(256, 1)
gemm_mma_kernel(const float* __restrict__ A,
                const __nv_bfloat16* __restrict__ Wt_hi, const __nv_bfloat16* __restrict__ Wt_lo,
                const float* __restrict__ bias, float* __restrict__ C,
                int M, int relu, int numTiles) {
    extern __shared__ __nv_bfloat16 sm[];
    uint32_t sbase = smem_u32(sm);
    int tid = threadIdx.x, wid = tid >> 5, lane = tid & 31;

    // ---- stage Wt hi/lo into padded smem (once per CTA) ----
    {
        const uint4* wh = (const uint4*)Wt_hi;     // 8 bf16 per uint4
        const uint4* wl = (const uint4*)Wt_lo;
        for (int i = tid; i < 2048; i += 256) {
            int r = i >> 4, c = i & 15;            // row n, 8-elem chunk c
            *(uint4*)(sm + S_WHI + r * ASTRIDE + c * 8) = wh[i];
            *(uint4*)(sm + S_WLO + r * ASTRIDE + c * 8) = wl[i];
        }
    }

    int mrow0 = (wid >> 1) << 5;                   // 0,32,64,96
    int ncol0 = (wid & 1) << 6;                    // 0,64

    // A fragment addresses (byte): row = mrow0 + lane%16, col = (lane/16)*8 + ks*16
    uint32_t aRow = (uint32_t)(mrow0 + (lane & 15));
    uint32_t aColB = (uint32_t)(((lane >> 4) << 3) * 2);   // bytes
    uint32_t aHi0 = sbase + (S_AHI * 2) + aRow * (ASTRIDE * 2) + aColB;
    uint32_t aHi1 = aHi0 + 16 * (ASTRIDE * 2);
    uint32_t aLo0 = aHi0 + (S_ALO - S_AHI) * 2;
    uint32_t aLo1 = aHi1 + (S_ALO - S_AHI) * 2;

    // B fragment addresses: n = ncol0 + npair*16 + (lane>>4)*8 + (lane&7), kcol = ((lane>>3)&1)*8 + ks*16
    uint32_t bN = (uint32_t)(ncol0 + ((lane >> 4) << 3) + (lane & 7));
    uint32_t bKB = (uint32_t)((((lane >> 3) & 1) << 3) * 2);
    uint32_t bHiBase = sbase + (S_WHI * 2) + bN * (ASTRIDE * 2) + bKB;
    uint32_t bLoBase = bHiBase + (S_WLO - S_WHI) * 2;

    for (int tile = blockIdx.x; tile < numTiles; tile += gridDim.x) {
        int row0 = tile << 7;
        __syncthreads();   // previous tile's reads done before restaging

        // ---- stage A tile: fp32 -> bf16 hi/lo ----
        #pragma unroll
        for (int it = 0; it < 16; it++) {
            int idx = it * 256 + tid;
            int r = idx >> 5;                  // 0..127
            int c4 = idx & 31;                 // float4 col
            int grow = row0 + r;
            float4 v = (grow < M) ? *(const float4*)(A + (size_t)grow * D + c4 * 4)
                                  : make_float4(0.f, 0.f, 0.f, 0.f);
            __nv_bfloat162 h01 = __floats2bfloat162_rn(v.x, v.y);
            __nv_bfloat162 h23 = __floats2bfloat162_rn(v.z, v.w);
            float lx = v.x - __bfloat162float(h01.x);
            float ly = v.y - __bfloat162float(h01.y);
            float lz = v.z - __bfloat162float(h23.x);
            float lw = v.w - __bfloat162float(h23.y);
            __nv_bfloat162 l01 = __floats2bfloat162_rn(lx, ly);
            __nv_bfloat162 l23 = __floats2bfloat162_rn(lz, lw);
            uint2 hp, lp;
            hp.x = *(uint32_t*)&h01; hp.y = *(uint32_t*)&h23;
            lp.x = *(uint32_t*)&l01; lp.y = *(uint32_t*)&l23;
            *(uint2*)(sm + S_AHI + r * ASTRIDE + c4 * 4) = hp;
            *(uint2*)(sm + S_ALO + r * ASTRIDE + c4 * 4) = lp;
        }
        __syncthreads();

        // ---- compute: 8 k-steps, 3 passes fused ----
        float acc[2][8][4];
        #pragma unroll
        for (int mt = 0; mt < 2; mt++)
            #pragma unroll
            for (int nt = 0; nt < 8; nt++)
                #pragma unroll
                for (int q = 0; q < 4; q++) acc[mt][nt][q] = 0.0f;

        #pragma unroll
        for (int ks = 0; ks < 8; ks++) {
            uint32_t koffB = (uint32_t)(ks * 32);      // 16 bf16 = 32 bytes per kstep
            uint32_t ah[2][4], al[2][4];
            ldsm4(ah[0], aHi0 + koffB);
            ldsm4(ah[1], aHi1 + koffB);
            ldsm4(al[0], aLo0 + koffB);
            ldsm4(al[1], aLo1 + koffB);
            uint32_t bh[8][2], bl[8][2];
            #pragma unroll
            for (int np = 0; np < 4; np++) {
                uint32_t r4[4];
                ldsm4(r4, bHiBase + (uint32_t)(np * 16 * ASTRIDE * 2) + koffB);
                bh[2 * np][0] = r4[0]; bh[2 * np][1] = r4[1];
                bh[2 * np + 1][0] = r4[2]; bh[2 * np + 1][1] = r4[3];
                ldsm4(r4, bLoBase + (uint32_t)(np * 16 * ASTRIDE * 2) + koffB);
                bl[2 * np][0] = r4[0]; bl[2 * np][1] = r4[1];
                bl[2 * np + 1][0] = r4[2]; bl[2 * np + 1][1] = r4[3];
            }
            #pragma unroll
            for (int mt = 0; mt < 2; mt++)
                #pragma unroll
                for (int nt = 0; nt < 8; nt++) {
                    mma16816(acc[mt][nt], ah[mt], bh[nt]);
                    mma16816(acc[mt][nt], ah[mt], bl[nt]);
                    mma16816(acc[mt][nt], al[mt], bh[nt]);
                }
        }

        // ---- epilogue ----
        int rbase = row0 + mrow0 + (lane >> 2);
        int cbase = ncol0 + ((lane & 3) << 1);
        #pragma unroll
        for (int mt = 0; mt < 2; mt++) {
            #pragma unroll
            for (int half = 0; half < 2; half++) {
                int gr = rbase + mt * 16 + half * 8;
                if (gr >= M) continue;
                float* cp = C + (size_t)gr * D;
                #pragma unroll
                for (int nt = 0; nt < 8; nt++) {
                    int col = cbase + nt * 8;
                    float o0 = acc[mt][nt][2 * half];
                    float o1 = acc[mt][nt][2 * half + 1];
                    if (bias) { o0 += bias[col]; o1 += bias[col + 1]; }
                    if (relu) { o0 = fmaxf(o0, 0.f); o1 = fmaxf(o1, 0.f); }
                    *(float2*)(cp + col) = make_float2(o0, o1);
                }
            }
        }
    }
}

// ---------------- aggregation: out[d] = sum_{src in CSR[d]} H[src] (+bias, relu) ----
__global__ void agg_kernel(const float* __restrict__ H, const int* __restrict__ rowptr,
                           const int* __restrict__ eidx, const float* __restrict__ bias,
                           float* __restrict__ out, int relu) {
    int d = blockIdx.x;
    int c = threadIdx.x;
    __shared__ int nb[128];
    int beg = rowptr[d], end = rowptr[d + 1];
    float acc = 0.0f;
    for (int j0 = beg; j0 < end; j0 += 128) {
        int cnt = min(128, end - j0);
        __syncthreads();
        if (c < cnt) nb[c] = eidx[j0 + c];
        __syncthreads();
        #pragma unroll 4
        for (int j = 0; j < cnt; j++)
            acc += H[(size_t)nb[j] * D + c];
    }
    float v = acc + bias[c];
    if (relu) v = fmaxf(v, 0.0f);
    out[(size_t)d * D + c] = v;
}

// ---------------- Z[q] = emb[src_q] * emb[dst_q] ----------------
__global__ void zbuild_kernel(const float* __restrict__ emb, const int* __restrict__ tedges,
                              float* __restrict__ Z, int NE) {
    int n4 = NE * 32;
    for (int idx = blockIdx.x * blockDim.x + threadIdx.x; idx < n4; idx += gridDim.x * blockDim.x) {
        int q = idx >> 5;
        int c4 = idx & 31;
        int s = tedges[2 * q];
        int d = tedges[2 * q + 1];
        float4 a = *(const float4*)(emb + (size_t)s * D + c4 * 4);
        float4 b = *(const float4*)(emb + (size_t)d * D + c4 * 4);
        ((float4*)Z)[idx] = make_float4(a.x * b.x, a.y * b.y, a.z * b.z, a.w * b.w);
    }
}

// ---------------- final: z@P3+pb3, L2-normalize, log_softmax ----------------
__global__ void final_kernel(const float* __restrict__ Zin, const float* __restrict__ P3,
                             const float* __restrict__ pb3, float* __restrict__ out, int NE) {
    int gw = (blockIdx.x * blockDim.x + threadIdx.x) >> 5;
    int lane = threadIdx.x & 31;
    if (gw >= NE) return;
    float4 v = ((const float4*)(Zin + (size_t)gw * D))[lane];
    int k = lane * 4;
    float p0 = v.x * P3[2 * k] + v.y * P3[2 * (k + 1)] + v.z * P3[2 * (k + 2)] + v.w * P3[2 * (k + 3)];
    float p1 = v.x * P3[2 * k + 1] + v.y * P3[2 * (k + 1) + 1] + v.z * P3[2 * (k + 2) + 1] + v.w * P3[2 * (k + 3) + 1];
    #pragma unroll
    for (int off = 16; off > 0; off >>= 1) {
        p0 += __shfl_xor_sync(0xFFFFFFFFu, p0, off);
        p1 += __shfl_xor_sync(0xFFFFFFFFu, p1, off);
    }
    if (lane == 0) {
        float z0 = p0 + pb3[0];
        float z1 = p1 + pb3[1];
        float nrm = fmaxf(sqrtf(z0 * z0 + z1 * z1), 1e-12f);
        z0 /= nrm; z1 /= nrm;
        float m = fmaxf(z0, z1);
        float lse = m + logf(expf(z0 - m) + expf(z1 - m));
        out[2 * gw]     = z0 - lse;
        out[2 * gw + 1] = z1 - lse;
    }
}

// ---------------- launch ----------------
extern "C" void kernel_launch(void* const* d_in, const int* in_sizes, int n_in,
                              void* d_out, int out_size) {
    const float* x    = (const float*)d_in[0];
    const int*   adj  = (const int*)d_in[1];
    const int*   tedg = (const int*)d_in[2];
    const float* W1 = (const float*)d_in[3];  const float* b1  = (const float*)d_in[4];
    const float* W2 = (const float*)d_in[5];  const float* b2  = (const float*)d_in[6];
    const float* W3 = (const float*)d_in[7];  const float* b3  = (const float*)d_in[8];
    const float* P1 = (const float*)d_in[9];  const float* pb1 = (const float*)d_in[10];
    const float* P2 = (const float*)d_in[11]; const float* pb2 = (const float*)d_in[12];
    const float* P3 = (const float*)d_in[13]; const float* pb3 = (const float*)d_in[14];
    float* out = (float*)d_out;

    int N  = in_sizes[0] / D;
    int E  = in_sizes[1] / 2;
    int NE = in_sizes[2] / 2;

    cudaFuncSetAttribute((const void*)gemm_mma_kernel,
                         cudaFuncAttributeMaxDynamicSharedMemorySize, SMEM_BYTES);

    float *bufA, *bufB, *Z, *Z2;
    int *deg, *rowptr, *cur, *eidx;
    __nv_bfloat16 *Whi, *Wlo;
    cudaGetSymbolAddress((void**)&bufA, g_bufA);
    cudaGetSymbolAddress((void**)&bufB, g_bufB);
    cudaGetSymbolAddress((void**)&Z,    g_Z);
    cudaGetSymbolAddress((void**)&Z2,   g_Z2);
    cudaGetSymbolAddress((void**)&deg,    g_deg);
    cudaGetSymbolAddress((void**)&rowptr, g_rowptr);
    cudaGetSymbolAddress((void**)&cur,    g_cur);
    cudaGetSymbolAddress((void**)&eidx,   g_eidx);
    cudaGetSymbolAddress((void**)&Whi,  g_Whi);
    cudaGetSymbolAddress((void**)&Wlo,  g_Wlo);

    const int* src = adj;
    const int* dst = adj + E;

    // ---- CSR build + weight prep ----
    zero_int_kernel<<<(N + 255) / 256, 256>>>(deg, N);
    hist_kernel<<<(E + 255) / 256, 256>>>(dst, E, deg);
    prep_weights_kernel<<<(5 * 16384 + 255) / 256, 256>>>(W1, W2, W3, P1, P2, Whi, Wlo);
    scan_kernel<<<1, 1024>>>(deg, rowptr, cur, N);
    fill_csr_kernel<<<(E + 255) / 256, 256>>>(src, dst, E, cur, eidx);

    int tilesN  = (N + 127) / 128;
    int tilesNE = (NE + 127) / 128;
    int gN  = tilesN  < 148 ? tilesN  : 148;
    int gNE = tilesNE < 148 ? tilesNE : 148;

    // ---- GCN trunk ----
    gemm_mma_kernel<<<gN, 256, SMEM_BYTES>>>(x,    Whi,             Wlo,             nullptr, bufA, N, 0, tilesN);
    agg_kernel<<<N, 128>>>(bufA, rowptr, eidx, b1, bufB, 1);
    gemm_mma_kernel<<<gN, 256, SMEM_BYTES>>>(bufB, Whi + 16384,     Wlo + 16384,     nullptr, bufA, N, 0, tilesN);
    agg_kernel<<<N, 128>>>(bufA, rowptr, eidx, b2, bufB, 1);
    gemm_mma_kernel<<<gN, 256, SMEM_BYTES>>>(bufB, Whi + 2 * 16384, Wlo + 2 * 16384, nullptr, bufA, N, 0, tilesN);
    agg_kernel<<<N, 128>>>(bufA, rowptr, eidx, b3, bufB, 0);   // emb

    // ---- link predictor ----
    zbuild_kernel<<<(NE * 32 + 255) / 256, 256>>>(bufB, tedg, Z, NE);
    gemm_mma_kernel<<<gNE, 256, SMEM_BYTES>>>(Z,  Whi + 3 * 16384, Wlo + 3 * 16384, pb1, Z2, NE, 1, tilesNE);
    gemm_mma_kernel<<<gNE, 256, SMEM_BYTES>>>(Z2, Whi + 4 * 16384, Wlo + 4 * 16384, pb2, Z,  NE, 1, tilesNE);
    final_kernel<<<(NE * 32 + 255) / 256, 256>>>(Z, P3, pb3, out, NE);
}

// round 4
// speedup vs baseline: 2.0701x; 1.2803x over previous
#include <cuda_runtime.h>
#include <cuda_bf16.h>
#include <math.h>
#include <stdint.h>

// ---------------- problem constants ----------------
#define MAXN 50000
#define MAXE 800000
#define MAXNE 100000
#define D 128

// ---------------- device scratch ----------------
__device__ float g_bufA[(size_t)MAXN * D];
__device__ float g_bufB[(size_t)MAXN * D];
__device__ float g_Z [(size_t)MAXNE * D];
__device__ float g_Z2[(size_t)MAXNE * D];
__device__ int   g_deg[MAXN];
__device__ int   g_rowptr[MAXN + 1];
__device__ int   g_cur[MAXN];
__device__ int   g_eidx[MAXE];
__device__ int   g_bsum[256];
// pre-transposed bf16 weights Wt[n][k] (5 x 128x128), hi & lo halves
__device__ __nv_bfloat16 g_Whi[5 * 16384];
__device__ __nv_bfloat16 g_Wlo[5 * 16384];

// ---------------- PTX helpers ----------------
__device__ __forceinline__ uint32_t smem_u32(const void* p) {
    uint32_t a;
    asm("{ .reg .u64 t; cvta.to.shared.u64 t, %1; cvt.u32.u64 %0, t; }" : "=r"(a) : "l"(p));
    return a;
}
__device__ __forceinline__ void ldsm4(uint32_t* r, uint32_t addr) {
    asm volatile("ldmatrix.sync.aligned.m8n8.x4.shared.b16 {%0,%1,%2,%3}, [%4];"
        : "=r"(r[0]), "=r"(r[1]), "=r"(r[2]), "=r"(r[3]) : "r"(addr));
}
__device__ __forceinline__ void mma16816(float* c, const uint32_t* a, const uint32_t* b) {
    asm volatile(
        "mma.sync.aligned.m16n8k16.row.col.f32.bf16.bf16.f32 "
        "{%0,%1,%2,%3}, {%4,%5,%6,%7}, {%8,%9}, {%0,%1,%2,%3};"
        : "+f"(c[0]), "+f"(c[1]), "+f"(c[2]), "+f"(c[3])
        : "r"(a[0]), "r"(a[1]), "r"(a[2]), "r"(a[3]), "r"(b[0]), "r"(b[1]));
}

// ---------------- CSR build kernels ----------------
__global__ void zero_int_kernel(int* p, int n) {
    for (int i = blockIdx.x * blockDim.x + threadIdx.x; i < n; i += gridDim.x * blockDim.x)
        p[i] = 0;
}
__global__ void hist_kernel(const int* __restrict__ dst, int E, int* __restrict__ deg) {
    for (int e = blockIdx.x * blockDim.x + threadIdx.x; e < E; e += gridDim.x * blockDim.x)
        atomicAdd(&deg[dst[e]], 1);
}

// --- 3-phase multi-block exclusive scan ---
// phase 1: per-block local exclusive into rowptr, block total into bsum
__global__ void scan1_kernel(const int* __restrict__ deg, int* __restrict__ rowptr,
                             int* __restrict__ bsum, int n) {
    __shared__ int wsum[32];
    int tid = threadIdx.x, lane = tid & 31, w = tid >> 5;
    int i = blockIdx.x * 1024 + tid;
    int v = (i < n) ? deg[i] : 0;
    int s = v;
    #pragma unroll
    for (int off = 1; off < 32; off <<= 1) {
        int t = __shfl_up_sync(0xFFFFFFFFu, s, off);
        if (lane >= off) s += t;
    }
    if (lane == 31) wsum[w] = s;
    __syncthreads();
    if (w == 0) {
        int ws = wsum[lane];
        #pragma unroll
        for (int off = 1; off < 32; off <<= 1) {
            int t = __shfl_up_sync(0xFFFFFFFFu, ws, off);
            if (lane >= off) ws += t;
        }
        wsum[lane] = ws;
    }
    __syncthreads();
    int prev = (w > 0) ? wsum[w - 1] : 0;
    int incl = prev + s;
    if (i < n) rowptr[i] = incl - v;           // local exclusive
    if (tid == 1023) bsum[blockIdx.x] = incl;  // block total
}
// phase 2: exclusive scan of block totals (nb <= 256, serial — tiny)
__global__ void scan2_kernel(int* bsum, int nb) {
    if (threadIdx.x == 0) {
        int acc = 0;
        for (int i = 0; i < nb; i++) { int t = bsum[i]; bsum[i] = acc; acc += t; }
    }
}
// phase 3: add block offsets, emit cur and rowptr[n]
__global__ void scan3_kernel(const int* __restrict__ deg, int* __restrict__ rowptr,
                             int* __restrict__ cur, const int* __restrict__ bsum, int n) {
    int i = blockIdx.x * 1024 + threadIdx.x;
    if (i >= n) return;
    int val = rowptr[i] + bsum[blockIdx.x];
    rowptr[i] = val;
    cur[i] = val;
    if (i == n - 1) rowptr[n] = val + deg[n - 1];
}

__global__ void fill_csr_kernel(const int* __restrict__ src, const int* __restrict__ dst,
                                int E, int* __restrict__ cur, int* __restrict__ eidx) {
    for (int e = blockIdx.x * blockDim.x + threadIdx.x; e < E; e += gridDim.x * blockDim.x) {
        int d = dst[e];
        int p = atomicAdd(&cur[d], 1);
        eidx[p] = src[e];
    }
}

// ---------------- weight prep: W[k][n] fp32 -> Wt[n][k] bf16 hi/lo ----------------
__global__ void prep_weights_kernel(const float* W1, const float* W2, const float* W3,
                                    const float* P1, const float* P2,
                                    __nv_bfloat16* hi, __nv_bfloat16* lo) {
    int idx = blockIdx.x * blockDim.x + threadIdx.x;
    if (idx >= 5 * 16384) return;
    int w = idx >> 14;
    int t = idx & 16383;
    int n = t >> 7;
    int k = t & 127;
    const float* Ws = (w == 0) ? W1 : (w == 1) ? W2 : (w == 2) ? W3 : (w == 3) ? P1 : P2;
    float v = Ws[(k << 7) | n];
    __nv_bfloat16 h = __float2bfloat16(v);
    float rem = v - __bfloat162float(h);
    __nv_bfloat16 l = __float2bfloat16(rem);
    hi[idx] = h;
    lo[idx] = l;
}

// ---------------- mma.sync GEMM: C[M,128] = A[M,128] @ W[128,128] (+bias)(+relu) ----
// 256 threads = 8 warps (4x2). Warp tile 32x64. bf16 hi/lo 3-pass.
#define ASTRIDE 136                       // padded row stride (bf16 elems)
#define S_AHI 0
#define S_ALO (128 * ASTRIDE)             // 17408
#define S_WHI (2 * 128 * ASTRIDE)
#define S_WLO (3 * 128 * ASTRIDE)
#define SMEM_ELEMS (4 * 128 * ASTRIDE)    // 69632 bf16
#define SMEM_BYTES (SMEM_ELEMS * 2)       // 139264 B

__global__ void __launch_bounds__(256, 1)
gemm_mma_kernel(const float* __restrict__ A,
                const __nv_bfloat16* __restrict__ Wt_hi, const __nv_bfloat16* __restrict__ Wt_lo,
                const float* __restrict__ bias, float* __restrict__ C,
                int M, int relu, int numTiles) {
    extern __shared__ __nv_bfloat16 sm[];
    uint32_t sbase = smem_u32(sm);
    int tid = threadIdx.x, wid = tid >> 5, lane = tid & 31;

    // ---- stage Wt hi/lo into padded smem (once per CTA) ----
    {
        const uint4* wh = (const uint4*)Wt_hi;     // 8 bf16 per uint4
        const uint4* wl = (const uint4*)Wt_lo;
        for (int i = tid; i < 2048; i += 256) {
            int r = i >> 4, c = i & 15;            // row n, 8-elem chunk c
            *(uint4*)(sm + S_WHI + r * ASTRIDE + c * 8) = wh[i];
            *(uint4*)(sm + S_WLO + r * ASTRIDE + c * 8) = wl[i];
        }
    }

    int mrow0 = (wid >> 1) << 5;                   // 0,32,64,96
    int ncol0 = (wid & 1) << 6;                    // 0,64

    uint32_t aRow = (uint32_t)(mrow0 + (lane & 15));
    uint32_t aColB = (uint32_t)(((lane >> 4) << 3) * 2);
    uint32_t aHi0 = sbase + (S_AHI * 2) + aRow * (ASTRIDE * 2) + aColB;
    uint32_t aHi1 = aHi0 + 16 * (ASTRIDE * 2);
    uint32_t aLo0 = aHi0 + (S_ALO - S_AHI) * 2;
    uint32_t aLo1 = aHi1 + (S_ALO - S_AHI) * 2;

    uint32_t bN = (uint32_t)(ncol0 + ((lane >> 4) << 3) + (lane & 7));
    uint32_t bKB = (uint32_t)((((lane >> 3) & 1) << 3) * 2);
    uint32_t bHiBase = sbase + (S_WHI * 2) + bN * (ASTRIDE * 2) + bKB;
    uint32_t bLoBase = bHiBase + (S_WLO - S_WHI) * 2;

    for (int tile = blockIdx.x; tile < numTiles; tile += gridDim.x) {
        int row0 = tile << 7;
        __syncthreads();

        // ---- stage A tile: fp32 -> bf16 hi/lo ----
        #pragma unroll
        for (int it = 0; it < 16; it++) {
            int idx = it * 256 + tid;
            int r = idx >> 5;
            int c4 = idx & 31;
            int grow = row0 + r;
            float4 v = (grow < M) ? *(const float4*)(A + (size_t)grow * D + c4 * 4)
                                  : make_float4(0.f, 0.f, 0.f, 0.f);
            __nv_bfloat162 h01 = __floats2bfloat162_rn(v.x, v.y);
            __nv_bfloat162 h23 = __floats2bfloat162_rn(v.z, v.w);
            float lx = v.x - __bfloat162float(h01.x);
            float ly = v.y - __bfloat162float(h01.y);
            float lz = v.z - __bfloat162float(h23.x);
            float lw = v.w - __bfloat162float(h23.y);
            __nv_bfloat162 l01 = __floats2bfloat162_rn(lx, ly);
            __nv_bfloat162 l23 = __floats2bfloat162_rn(lz, lw);
            uint2 hp, lp;
            hp.x = *(uint32_t*)&h01; hp.y = *(uint32_t*)&h23;
            lp.x = *(uint32_t*)&l01; lp.y = *(uint32_t*)&l23;
            *(uint2*)(sm + S_AHI + r * ASTRIDE + c4 * 4) = hp;
            *(uint2*)(sm + S_ALO + r * ASTRIDE + c4 * 4) = lp;
        }
        __syncthreads();

        // ---- compute: 8 k-steps, 3 passes fused ----
        float acc[2][8][4];
        #pragma unroll
        for (int mt = 0; mt < 2; mt++)
            #pragma unroll
            for (int nt = 0; nt < 8; nt++)
                #pragma unroll
                for (int q = 0; q < 4; q++) acc[mt][nt][q] = 0.0f;

        #pragma unroll
        for (int ks = 0; ks < 8; ks++) {
            uint32_t koffB = (uint32_t)(ks * 32);
            uint32_t ah[2][4], al[2][4];
            ldsm4(ah[0], aHi0 + koffB);
            ldsm4(ah[1], aHi1 + koffB);
            ldsm4(al[0], aLo0 + koffB);
            ldsm4(al[1], aLo1 + koffB);
            uint32_t bh[8][2], bl[8][2];
            #pragma unroll
            for (int np = 0; np < 4; np++) {
                uint32_t r4[4];
                ldsm4(r4, bHiBase + (uint32_t)(np * 16 * ASTRIDE * 2) + koffB);
                bh[2 * np][0] = r4[0]; bh[2 * np][1] = r4[1];
                bh[2 * np + 1][0] = r4[2]; bh[2 * np + 1][1] = r4[3];
                ldsm4(r4, bLoBase + (uint32_t)(np * 16 * ASTRIDE * 2) + koffB);
                bl[2 * np][0] = r4[0]; bl[2 * np][1] = r4[1];
                bl[2 * np + 1][0] = r4[2]; bl[2 * np + 1][1] = r4[3];
            }
            #pragma unroll
            for (int mt = 0; mt < 2; mt++)
                #pragma unroll
                for (int nt = 0; nt < 8; nt++) {
                    mma16816(acc[mt][nt], ah[mt], bh[nt]);
                    mma16816(acc[mt][nt], ah[mt], bl[nt]);
                    mma16816(acc[mt][nt], al[mt], bh[nt]);
                }
        }

        // ---- epilogue ----
        int rbase = row0 + mrow0 + (lane >> 2);
        int cbase = ncol0 + ((lane & 3) << 1);
        #pragma unroll
        for (int mt = 0; mt < 2; mt++) {
            #pragma unroll
            for (int half = 0; half < 2; half++) {
                int gr = rbase + mt * 16 + half * 8;
                if (gr >= M) continue;
                float* cp = C + (size_t)gr * D;
                #pragma unroll
                for (int nt = 0; nt < 8; nt++) {
                    int col = cbase + nt * 8;
                    float o0 = acc[mt][nt][2 * half];
                    float o1 = acc[mt][nt][2 * half + 1];
                    if (bias) { o0 += bias[col]; o1 += bias[col + 1]; }
                    if (relu) { o0 = fmaxf(o0, 0.f); o1 = fmaxf(o1, 0.f); }
                    *(float2*)(cp + col) = make_float2(o0, o1);
                }
            }
        }
    }
}

// ---------------- aggregation: warp-per-dst, lane = 4 columns (float4) ----------------
__global__ void agg_kernel(const float* __restrict__ H, const int* __restrict__ rowptr,
                           const int* __restrict__ eidx, const float* __restrict__ bias,
                           float* __restrict__ out, int relu, int N) {
    int gw = (blockIdx.x * blockDim.x + threadIdx.x) >> 5;
    int lane = threadIdx.x & 31;
    if (gw >= N) return;
    int beg = rowptr[gw], end = rowptr[gw + 1];
    float4 acc = make_float4(0.f, 0.f, 0.f, 0.f);
    for (int j0 = beg; j0 < end; j0 += 32) {
        int cnt = min(32, end - j0);
        int e = (lane < cnt) ? eidx[j0 + lane] : 0;
        for (int t = 0; t < cnt; t++) {
            int s = __shfl_sync(0xFFFFFFFFu, e, t);
            float4 v = *(const float4*)(H + (size_t)s * D + (lane << 2));
            acc.x += v.x; acc.y += v.y; acc.z += v.z; acc.w += v.w;
        }
    }
    float4 bv = *(const float4*)(bias + (lane << 2));
    acc.x += bv.x; acc.y += bv.y; acc.z += bv.z; acc.w += bv.w;
    if (relu) {
        acc.x = fmaxf(acc.x, 0.f); acc.y = fmaxf(acc.y, 0.f);
        acc.z = fmaxf(acc.z, 0.f); acc.w = fmaxf(acc.w, 0.f);
    }
    *(float4*)(out + (size_t)gw * D + (lane << 2)) = acc;
}

// ---------------- Z[q] = emb[src_q] * emb[dst_q] ----------------
__global__ void zbuild_kernel(const float* __restrict__ emb, const int* __restrict__ tedges,
                              float* __restrict__ Z, int NE) {
    int n4 = NE * 32;
    for (int idx = blockIdx.x * blockDim.x + threadIdx.x; idx < n4; idx += gridDim.x * blockDim.x) {
        int q = idx >> 5;
        int c4 = idx & 31;
        int s = tedges[2 * q];
        int d = tedges[2 * q + 1];
        float4 a = *(const float4*)(emb + (size_t)s * D + c4 * 4);
        float4 b = *(const float4*)(emb + (size_t)d * D + c4 * 4);
        ((float4*)Z)[idx] = make_float4(a.x * b.x, a.y * b.y, a.z * b.z, a.w * b.w);
    }
}

// ---------------- final: z@P3+pb3, L2-normalize, log_softmax ----------------
__global__ void final_kernel(const float* __restrict__ Zin, const float* __restrict__ P3,
                             const float* __restrict__ pb3, float* __restrict__ out, int NE) {
    int gw = (blockIdx.x * blockDim.x + threadIdx.x) >> 5;
    int lane = threadIdx.x & 31;
    if (gw >= NE) return;
    float4 v = ((const float4*)(Zin + (size_t)gw * D))[lane];
    int k = lane * 4;
    float p0 = v.x * P3[2 * k] + v.y * P3[2 * (k + 1)] + v.z * P3[2 * (k + 2)] + v.w * P3[2 * (k + 3)];
    float p1 = v.x * P3[2 * k + 1] + v.y * P3[2 * (k + 1) + 1] + v.z * P3[2 * (k + 2) + 1] + v.w * P3[2 * (k + 3) + 1];
    #pragma unroll
    for (int off = 16; off > 0; off >>= 1) {
        p0 += __shfl_xor_sync(0xFFFFFFFFu, p0, off);
        p1 += __shfl_xor_sync(0xFFFFFFFFu, p1, off);
    }
    if (lane == 0) {
        float z0 = p0 + pb3[0];
        float z1 = p1 + pb3[1];
        float nrm = fmaxf(sqrtf(z0 * z0 + z1 * z1), 1e-12f);
        z0 /= nrm; z1 /= nrm;
        float m = fmaxf(z0, z1);
        float lse = m + logf(expf(z0 - m) + expf(z1 - m));
        out[2 * gw]     = z0 - lse;
        out[2 * gw + 1] = z1 - lse;
    }
}

// ---------------- launch ----------------
extern "C" void kernel_launch(void* const* d_in, const int* in_sizes, int n_in,
                              void* d_out, int out_size) {
    const float* x    = (const float*)d_in[0];
    const int*   adj  = (const int*)d_in[1];
    const int*   tedg = (const int*)d_in[2];
    const float* W1 = (const float*)d_in[3];  const float* b1  = (const float*)d_in[4];
    const float* W2 = (const float*)d_in[5];  const float* b2  = (const float*)d_in[6];
    const float* W3 = (const float*)d_in[7];  const float* b3  = (const float*)d_in[8];
    const float* P1 = (const float*)d_in[9];  const float* pb1 = (const float*)d_in[10];
    const float* P2 = (const float*)d_in[11]; const float* pb2 = (const float*)d_in[12];
    const float* P3 = (const float*)d_in[13]; const float* pb3 = (const float*)d_in[14];
    float* out = (float*)d_out;

    int N  = in_sizes[0] / D;
    int E  = in_sizes[1] / 2;
    int NE = in_sizes[2] / 2;

    cudaFuncSetAttribute((const void*)gemm_mma_kernel,
                         cudaFuncAttributeMaxDynamicSharedMemorySize, SMEM_BYTES);

    float *bufA, *bufB, *Z, *Z2;
    int *deg, *rowptr, *cur, *eidx, *bsum;
    __nv_bfloat16 *Whi, *Wlo;
    cudaGetSymbolAddress((void**)&bufA, g_bufA);
    cudaGetSymbolAddress((void**)&bufB, g_bufB);
    cudaGetSymbolAddress((void**)&Z,    g_Z);
    cudaGetSymbolAddress((void**)&Z2,   g_Z2);
    cudaGetSymbolAddress((void**)&deg,    g_deg);
    cudaGetSymbolAddress((void**)&rowptr, g_rowptr);
    cudaGetSymbolAddress((void**)&cur,    g_cur);
    cudaGetSymbolAddress((void**)&eidx,   g_eidx);
    cudaGetSymbolAddress((void**)&bsum,   g_bsum);
    cudaGetSymbolAddress((void**)&Whi,  g_Whi);
    cudaGetSymbolAddress((void**)&Wlo,  g_Wlo);

    const int* src = adj;
    const int* dst = adj + E;

    int nScanBlk = (N + 1023) / 1024;

    // ---- CSR build + weight prep ----
    zero_int_kernel<<<(N + 255) / 256, 256>>>(deg, N);
    hist_kernel<<<(E + 255) / 256, 256>>>(dst, E, deg);
    prep_weights_kernel<<<(5 * 16384 + 255) / 256, 256>>>(W1, W2, W3, P1, P2, Whi, Wlo);
    scan1_kernel<<<nScanBlk, 1024>>>(deg, rowptr, bsum, N);
    scan2_kernel<<<1, 32>>>(bsum, nScanBlk);
    scan3_kernel<<<nScanBlk, 1024>>>(deg, rowptr, cur, bsum, N);
    fill_csr_kernel<<<(E + 255) / 256, 256>>>(src, dst, E, cur, eidx);

    int tilesN  = (N + 127) / 128;
    int tilesNE = (NE + 127) / 128;
    int gN  = tilesN  < 148 ? tilesN  : 148;
    int gNE = tilesNE < 148 ? tilesNE : 148;
    int aggBlk = (N * 32 + 255) / 256;

    // ---- GCN trunk ----
    gemm_mma_kernel<<<gN, 256, SMEM_BYTES>>>(x,    Whi,             Wlo,             nullptr, bufA, N, 0, tilesN);
    agg_kernel<<<aggBlk, 256>>>(bufA, rowptr, eidx, b1, bufB, 1, N);
    gemm_mma_kernel<<<gN, 256, SMEM_BYTES>>>(bufB, Whi + 16384,     Wlo + 16384,     nullptr, bufA, N, 0, tilesN);
    agg_kernel<<<aggBlk, 256>>>(bufA, rowptr, eidx, b2, bufB, 1, N);
    gemm_mma_kernel<<<gN, 256, SMEM_BYTES>>>(bufB, Whi + 2 * 16384, Wlo + 2 * 16384, nullptr, bufA, N, 0, tilesN);
    agg_kernel<<<aggBlk, 256>>>(bufA, rowptr, eidx, b3, bufB, 0, N);   // emb

    // ---- link predictor ----
    zbuild_kernel<<<(NE * 32 + 255) / 256, 256>>>(bufB, tedg, Z, NE);
    gemm_mma_kernel<<<gNE, 256, SMEM_BYTES>>>(Z,  Whi + 3 * 16384, Wlo + 3 * 16384, pb1, Z2, NE, 1, tilesNE);
    gemm_mma_kernel<<<gNE, 256, SMEM_BYTES>>>(Z2, Whi + 4 * 16384, Wlo + 4 * 16384, pb2, Z,  NE, 1, tilesNE);
    final_kernel<<<(NE * 32 + 255) / 256, 256>>>(Z, P3, pb3, out, NE);
}

// round 5
// speedup vs baseline: 2.3560x; 1.1381x over previous
#include <cuda_runtime.h>
#include <cuda_bf16.h>
#include <math.h>
#include <stdint.h>

// ---------------- problem constants ----------------
#define MAXN 50000
#define MAXE 800000
#define MAXNE 100000
#define D 128

// ---------------- device scratch ----------------
__device__ float g_bufA[(size_t)MAXN * D];
__device__ float g_bufB[(size_t)MAXN * D];
__device__ float g_Z2[(size_t)MAXNE * D];
__device__ int   g_deg[MAXN];
__device__ int   g_rowptr[MAXN + 1];
__device__ int   g_cur[MAXN];
__device__ int   g_eidx[MAXE];
__device__ int   g_bsum[256];
// pre-transposed bf16 weights Wt[n][k] (5 x 128x128), hi & lo halves
__device__ __nv_bfloat16 g_Whi[5 * 16384];
__device__ __nv_bfloat16 g_Wlo[5 * 16384];

// ---------------- PTX helpers ----------------
__device__ __forceinline__ uint32_t smem_u32(const void* p) {
    uint32_t a;
    asm("{ .reg .u64 t; cvta.to.shared.u64 t, %1; cvt.u32.u64 %0, t; }" : "=r"(a) : "l"(p));
    return a;
}
__device__ __forceinline__ void ldsm4(uint32_t* r, uint32_t addr) {
    asm volatile("ldmatrix.sync.aligned.m8n8.x4.shared.b16 {%0,%1,%2,%3}, [%4];"
        : "=r"(r[0]), "=r"(r[1]), "=r"(r[2]), "=r"(r[3]) : "r"(addr));
}
__device__ __forceinline__ void mma16816(float* c, const uint32_t* a, const uint32_t* b) {
    asm volatile(
        "mma.sync.aligned.m16n8k16.row.col.f32.bf16.bf16.f32 "
        "{%0,%1,%2,%3}, {%4,%5,%6,%7}, {%8,%9}, {%0,%1,%2,%3};"
        : "+f"(c[0]), "+f"(c[1]), "+f"(c[2]), "+f"(c[3])
        : "r"(a[0]), "r"(a[1]), "r"(a[2]), "r"(a[3]), "r"(b[0]), "r"(b[1]));
}

// ---------------- CSR build kernels ----------------
__global__ void zero_int_kernel(int* p, int n) {
    for (int i = blockIdx.x * blockDim.x + threadIdx.x; i < n; i += gridDim.x * blockDim.x)
        p[i] = 0;
}
__global__ void hist_kernel(const int* __restrict__ dst, int E, int* __restrict__ deg) {
    for (int e = blockIdx.x * blockDim.x + threadIdx.x; e < E; e += gridDim.x * blockDim.x)
        atomicAdd(&deg[dst[e]], 1);
}

// --- 3-phase multi-block exclusive scan ---
__global__ void scan1_kernel(const int* __restrict__ deg, int* __restrict__ rowptr,
                             int* __restrict__ bsum, int n) {
    __shared__ int wsum[32];
    int tid = threadIdx.x, lane = tid & 31, w = tid >> 5;
    int i = blockIdx.x * 1024 + tid;
    int v = (i < n) ? deg[i] : 0;
    int s = v;
    #pragma unroll
    for (int off = 1; off < 32; off <<= 1) {
        int t = __shfl_up_sync(0xFFFFFFFFu, s, off);
        if (lane >= off) s += t;
    }
    if (lane == 31) wsum[w] = s;
    __syncthreads();
    if (w == 0) {
        int ws = wsum[lane];
        #pragma unroll
        for (int off = 1; off < 32; off <<= 1) {
            int t = __shfl_up_sync(0xFFFFFFFFu, ws, off);
            if (lane >= off) ws += t;
        }
        wsum[lane] = ws;
    }
    __syncthreads();
    int prev = (w > 0) ? wsum[w - 1] : 0;
    int incl = prev + s;
    if (i < n) rowptr[i] = incl - v;
    if (tid == 1023) bsum[blockIdx.x] = incl;
}
// phase 2: single-warp shuffle exclusive scan of block totals
__global__ void scan2_kernel(int* bsum, int nb) {
    int lane = threadIdx.x;
    int carry = 0;
    for (int base = 0; base < nb; base += 32) {
        int i = base + lane;
        int v = (i < nb) ? bsum[i] : 0;
        int s = v;
        #pragma unroll
        for (int off = 1; off < 32; off <<= 1) {
            int t = __shfl_up_sync(0xFFFFFFFFu, s, off);
            if (lane >= off) s += t;
        }
        if (i < nb) bsum[i] = carry + s - v;
        carry += __shfl_sync(0xFFFFFFFFu, s, 31);
    }
}
__global__ void scan3_kernel(const int* __restrict__ deg, int* __restrict__ rowptr,
                             int* __restrict__ cur, const int* __restrict__ bsum, int n) {
    int i = blockIdx.x * 1024 + threadIdx.x;
    if (i >= n) return;
    int val = rowptr[i] + bsum[blockIdx.x];
    rowptr[i] = val;
    cur[i] = val;
    if (i == n - 1) rowptr[n] = val + deg[n - 1];
}
__global__ void fill_csr_kernel(const int* __restrict__ src, const int* __restrict__ dst,
                                int E, int* __restrict__ cur, int* __restrict__ eidx) {
    for (int e = blockIdx.x * blockDim.x + threadIdx.x; e < E; e += gridDim.x * blockDim.x) {
        int d = dst[e];
        int p = atomicAdd(&cur[d], 1);
        eidx[p] = src[e];
    }
}

// ---------------- weight prep: W[k][n] fp32 -> Wt[n][k] bf16 hi/lo ----------------
__global__ void prep_weights_kernel(const float* W1, const float* W2, const float* W3,
                                    const float* P1, const float* P2,
                                    __nv_bfloat16* hi, __nv_bfloat16* lo) {
    int idx = blockIdx.x * blockDim.x + threadIdx.x;
    if (idx >= 5 * 16384) return;
    int w = idx >> 14;
    int t = idx & 16383;
    int n = t >> 7;
    int k = t & 127;
    const float* Ws = (w == 0) ? W1 : (w == 1) ? W2 : (w == 2) ? W3 : (w == 3) ? P1 : P2;
    float v = Ws[(k << 7) | n];
    __nv_bfloat16 h = __float2bfloat16(v);
    float rem = v - __bfloat162float(h);
    __nv_bfloat16 l = __float2bfloat16(rem);
    hi[idx] = h;
    lo[idx] = l;
}

// ---------------- mma.sync GEMM (+optional gather staging, +optional fused final) ----
#define ASTRIDE 136
#define S_AHI 0
#define S_ALO (128 * ASTRIDE)
#define S_WHI (2 * 128 * ASTRIDE)
#define S_WLO (3 * 128 * ASTRIDE)
#define SMEM_ELEMS (4 * 128 * ASTRIDE)        // 69632 bf16 = 139264 B
// float regions appended after bf16 tiles:
//   fpart[256]  : cross-warp partial dot (128 rows x 2)
//   fP3[256]    : P3 table, fpb3[2]
#define SMEM_BYTES (SMEM_ELEMS * 2 + (256 + 256 + 8) * 4)

// mode: 0 = plain, 1 = gather staging (A row q = emb[t2q]*emb[t2q+1]),
//       2 = fused final epilogue (z@P3, normalize, log_softmax -> outF)
__global__ void __launch_bounds__(256, 1)
gemm_mma_kernel(const float* __restrict__ A, const int* __restrict__ tedg,
                const __nv_bfloat16* __restrict__ Wt_hi, const __nv_bfloat16* __restrict__ Wt_lo,
                const float* __restrict__ bias, float* __restrict__ C,
                const float* __restrict__ P3, const float* __restrict__ pb3,
                float* __restrict__ outF,
                int M, int relu, int numTiles, int mode) {
    extern __shared__ __nv_bfloat16 sm[];
    uint32_t sbase = smem_u32(sm);
    float* fpart = (float*)(sm + SMEM_ELEMS);
    float* fP3 = fpart + 256;
    float* fpb3 = fP3 + 256;
    int tid = threadIdx.x, wid = tid >> 5, lane = tid & 31;

    // ---- stage Wt hi/lo into padded smem (once per CTA) ----
    {
        const uint4* wh = (const uint4*)Wt_hi;
        const uint4* wl = (const uint4*)Wt_lo;
        for (int i = tid; i < 2048; i += 256) {
            int r = i >> 4, c = i & 15;
            *(uint4*)(sm + S_WHI + r * ASTRIDE + c * 8) = wh[i];
            *(uint4*)(sm + S_WLO + r * ASTRIDE + c * 8) = wl[i];
        }
        if (mode == 2) {
            fP3[tid] = P3[tid];
            if (tid < 2) fpb3[tid] = pb3[tid];
        }
    }

    int mrow0 = (wid >> 1) << 5;
    int ncol0 = (wid & 1) << 6;

    uint32_t aRow = (uint32_t)(mrow0 + (lane & 15));
    uint32_t aColB = (uint32_t)(((lane >> 4) << 3) * 2);
    uint32_t aHi0 = sbase + (S_AHI * 2) + aRow * (ASTRIDE * 2) + aColB;
    uint32_t aHi1 = aHi0 + 16 * (ASTRIDE * 2);
    uint32_t aLo0 = aHi0 + (S_ALO - S_AHI) * 2;
    uint32_t aLo1 = aHi1 + (S_ALO - S_AHI) * 2;

    uint32_t bN = (uint32_t)(ncol0 + ((lane >> 4) << 3) + (lane & 7));
    uint32_t bKB = (uint32_t)((((lane >> 3) & 1) << 3) * 2);
    uint32_t bHiBase = sbase + (S_WHI * 2) + bN * (ASTRIDE * 2) + bKB;
    uint32_t bLoBase = bHiBase + (S_WLO - S_WHI) * 2;

    for (int tile = blockIdx.x; tile < numTiles; tile += gridDim.x) {
        int row0 = tile << 7;
        __syncthreads();

        // ---- stage A tile: fp32 (direct or gathered product) -> bf16 hi/lo ----
        #pragma unroll
        for (int it = 0; it < 16; it++) {
            int idx = it * 256 + tid;
            int r = idx >> 5;
            int c4 = idx & 31;
            int grow = row0 + r;
            float4 v;
            if (grow < M) {
                if (mode == 1) {
                    int s = tedg[2 * grow];
                    int d = tedg[2 * grow + 1];
                    float4 a = *(const float4*)(A + (size_t)s * D + c4 * 4);
                    float4 b = *(const float4*)(A + (size_t)d * D + c4 * 4);
                    v = make_float4(a.x * b.x, a.y * b.y, a.z * b.z, a.w * b.w);
                } else {
                    v = *(const float4*)(A + (size_t)grow * D + c4 * 4);
                }
            } else {
                v = make_float4(0.f, 0.f, 0.f, 0.f);
            }
            __nv_bfloat162 h01 = __floats2bfloat162_rn(v.x, v.y);
            __nv_bfloat162 h23 = __floats2bfloat162_rn(v.z, v.w);
            float lx = v.x - __bfloat162float(h01.x);
            float ly = v.y - __bfloat162float(h01.y);
            float lz = v.z - __bfloat162float(h23.x);
            float lw = v.w - __bfloat162float(h23.y);
            __nv_bfloat162 l01 = __floats2bfloat162_rn(lx, ly);
            __nv_bfloat162 l23 = __floats2bfloat162_rn(lz, lw);
            uint2 hp, lp;
            hp.x = *(uint32_t*)&h01; hp.y = *(uint32_t*)&h23;
            lp.x = *(uint32_t*)&l01; lp.y = *(uint32_t*)&l23;
            *(uint2*)(sm + S_AHI + r * ASTRIDE + c4 * 4) = hp;
            *(uint2*)(sm + S_ALO + r * ASTRIDE + c4 * 4) = lp;
        }
        __syncthreads();

        // ---- compute: 8 k-steps, 3 passes fused ----
        float acc[2][8][4];
        #pragma unroll
        for (int mt = 0; mt < 2; mt++)
            #pragma unroll
            for (int nt = 0; nt < 8; nt++)
                #pragma unroll
                for (int q = 0; q < 4; q++) acc[mt][nt][q] = 0.0f;

        #pragma unroll
        for (int ks = 0; ks < 8; ks++) {
            uint32_t koffB = (uint32_t)(ks * 32);
            uint32_t ah[2][4], al[2][4];
            ldsm4(ah[0], aHi0 + koffB);
            ldsm4(ah[1], aHi1 + koffB);
            ldsm4(al[0], aLo0 + koffB);
            ldsm4(al[1], aLo1 + koffB);
            uint32_t bh[8][2], bl[8][2];
            #pragma unroll
            for (int np = 0; np < 4; np++) {
                uint32_t r4[4];
                ldsm4(r4, bHiBase + (uint32_t)(np * 16 * ASTRIDE * 2) + koffB);
                bh[2 * np][0] = r4[0]; bh[2 * np][1] = r4[1];
                bh[2 * np + 1][0] = r4[2]; bh[2 * np + 1][1] = r4[3];
                ldsm4(r4, bLoBase + (uint32_t)(np * 16 * ASTRIDE * 2) + koffB);
                bl[2 * np][0] = r4[0]; bl[2 * np][1] = r4[1];
                bl[2 * np + 1][0] = r4[2]; bl[2 * np + 1][1] = r4[3];
            }
            #pragma unroll
            for (int mt = 0; mt < 2; mt++)
                #pragma unroll
                for (int nt = 0; nt < 8; nt++) {
                    mma16816(acc[mt][nt], ah[mt], bh[nt]);
                    mma16816(acc[mt][nt], ah[mt], bl[nt]);
                    mma16816(acc[mt][nt], al[mt], bh[nt]);
                }
        }

        int cbase = ncol0 + ((lane & 3) << 1);

        if (mode == 2) {
            // ---- fused final epilogue: z = relu(acc+bias); p = z @ P3; reduce; out ----
            float q0s[4], q1s[4];
            #pragma unroll
            for (int mt = 0; mt < 2; mt++) {
                #pragma unroll
                for (int half = 0; half < 2; half++) {
                    float q0 = 0.f, q1 = 0.f;
                    #pragma unroll
                    for (int nt = 0; nt < 8; nt++) {
                        int col = cbase + nt * 8;
                        float z0 = fmaxf(acc[mt][nt][2 * half] + bias[col], 0.f);
                        float z1 = fmaxf(acc[mt][nt][2 * half + 1] + bias[col + 1], 0.f);
                        q0 += z0 * fP3[2 * col] + z1 * fP3[2 * (col + 1)];
                        q1 += z0 * fP3[2 * col + 1] + z1 * fP3[2 * (col + 1) + 1];
                    }
                    q0 += __shfl_xor_sync(0xFFFFFFFFu, q0, 1);
                    q0 += __shfl_xor_sync(0xFFFFFFFFu, q0, 2);
                    q1 += __shfl_xor_sync(0xFFFFFFFFu, q1, 1);
                    q1 += __shfl_xor_sync(0xFFFFFFFFu, q1, 2);
                    q0s[mt * 2 + half] = q0;
                    q1s[mt * 2 + half] = q1;
                    if (ncol0 == 0 && (lane & 3) == 0) {
                        int rl = mrow0 + mt * 16 + half * 8 + (lane >> 2);
                        fpart[2 * rl] = q0;
                        fpart[2 * rl + 1] = q1;
                    }
                }
            }
            __syncthreads();
            if (ncol0 == 64 && (lane & 3) == 0) {
                #pragma unroll
                for (int mt = 0; mt < 2; mt++) {
                    #pragma unroll
                    for (int half = 0; half < 2; half++) {
                        int rl = mrow0 + mt * 16 + half * 8 + (lane >> 2);
                        int gr = row0 + rl;
                        if (gr < M) {
                            float z0 = q0s[mt * 2 + half] + fpart[2 * rl] + fpb3[0];
                            float z1 = q1s[mt * 2 + half] + fpart[2 * rl + 1] + fpb3[1];
                            float nrm = fmaxf(sqrtf(z0 * z0 + z1 * z1), 1e-12f);
                            z0 /= nrm; z1 /= nrm;
                            float mm = fmaxf(z0, z1);
                            float lse = mm + logf(expf(z0 - mm) + expf(z1 - mm));
                            outF[2 * gr]     = z0 - lse;
                            outF[2 * gr + 1] = z1 - lse;
                        }
                    }
                }
            }
        } else {
            // ---- normal epilogue ----
            int rbase = row0 + mrow0 + (lane >> 2);
            #pragma unroll
            for (int mt = 0; mt < 2; mt++) {
                #pragma unroll
                for (int half = 0; half < 2; half++) {
                    int gr = rbase + mt * 16 + half * 8;
                    if (gr >= M) continue;
                    float* cp = C + (size_t)gr * D;
                    #pragma unroll
                    for (int nt = 0; nt < 8; nt++) {
                        int col = cbase + nt * 8;
                        float o0 = acc[mt][nt][2 * half];
                        float o1 = acc[mt][nt][2 * half + 1];
                        if (bias) { o0 += bias[col]; o1 += bias[col + 1]; }
                        if (relu) { o0 = fmaxf(o0, 0.f); o1 = fmaxf(o1, 0.f); }
                        *(float2*)(cp + col) = make_float2(o0, o1);
                    }
                }
            }
        }
    }
}

// ---------------- aggregation: warp-per-dst, lane = 4 columns (float4) ----------------
__global__ void agg_kernel(const float* __restrict__ H, const int* __restrict__ rowptr,
                           const int* __restrict__ eidx, const float* __restrict__ bias,
                           float* __restrict__ out, int relu, int N) {
    int gw = (blockIdx.x * blockDim.x + threadIdx.x) >> 5;
    int lane = threadIdx.x & 31;
    if (gw >= N) return;
    int beg = rowptr[gw], end = rowptr[gw + 1];
    float4 acc = make_float4(0.f, 0.f, 0.f, 0.f);
    for (int j0 = beg; j0 < end; j0 += 32) {
        int cnt = min(32, end - j0);
        int e = (lane < cnt) ? eidx[j0 + lane] : 0;
        for (int t = 0; t < cnt; t++) {
            int s = __shfl_sync(0xFFFFFFFFu, e, t);
            float4 v = *(const float4*)(H + (size_t)s * D + (lane << 2));
            acc.x += v.x; acc.y += v.y; acc.z += v.z; acc.w += v.w;
        }
    }
    float4 bv = *(const float4*)(bias + (lane << 2));
    acc.x += bv.x; acc.y += bv.y; acc.z += bv.z; acc.w += bv.w;
    if (relu) {
        acc.x = fmaxf(acc.x, 0.f); acc.y = fmaxf(acc.y, 0.f);
        acc.z = fmaxf(acc.z, 0.f); acc.w = fmaxf(acc.w, 0.f);
    }
    *(float4*)(out + (size_t)gw * D + (lane << 2)) = acc;
}

// ---------------- launch ----------------
extern "C" void kernel_launch(void* const* d_in, const int* in_sizes, int n_in,
                              void* d_out, int out_size) {
    const float* x    = (const float*)d_in[0];
    const int*   adj  = (const int*)d_in[1];
    const int*   tedg = (const int*)d_in[2];
    const float* W1 = (const float*)d_in[3];  const float* b1  = (const float*)d_in[4];
    const float* W2 = (const float*)d_in[5];  const float* b2  = (const float*)d_in[6];
    const float* W3 = (const float*)d_in[7];  const float* b3  = (const float*)d_in[8];
    const float* P1 = (const float*)d_in[9];  const float* pb1 = (const float*)d_in[10];
    const float* P2 = (const float*)d_in[11]; const float* pb2 = (const float*)d_in[12];
    const float* P3 = (const float*)d_in[13]; const float* pb3 = (const float*)d_in[14];
    float* out = (float*)d_out;

    int N  = in_sizes[0] / D;
    int E  = in_sizes[1] / 2;
    int NE = in_sizes[2] / 2;

    cudaFuncSetAttribute((const void*)gemm_mma_kernel,
                         cudaFuncAttributeMaxDynamicSharedMemorySize, SMEM_BYTES);

    float *bufA, *bufB, *Z2;
    int *deg, *rowptr, *cur, *eidx, *bsum;
    __nv_bfloat16 *Whi, *Wlo;
    cudaGetSymbolAddress((void**)&bufA, g_bufA);
    cudaGetSymbolAddress((void**)&bufB, g_bufB);
    cudaGetSymbolAddress((void**)&Z2,   g_Z2);
    cudaGetSymbolAddress((void**)&deg,    g_deg);
    cudaGetSymbolAddress((void**)&rowptr, g_rowptr);
    cudaGetSymbolAddress((void**)&cur,    g_cur);
    cudaGetSymbolAddress((void**)&eidx,   g_eidx);
    cudaGetSymbolAddress((void**)&bsum,   g_bsum);
    cudaGetSymbolAddress((void**)&Whi,  g_Whi);
    cudaGetSymbolAddress((void**)&Wlo,  g_Wlo);

    const int* src = adj;
    const int* dst = adj + E;

    int nScanBlk = (N + 1023) / 1024;

    // ---- CSR build + weight prep ----
    zero_int_kernel<<<(N + 255) / 256, 256>>>(deg, N);
    hist_kernel<<<(E + 255) / 256, 256>>>(dst, E, deg);
    prep_weights_kernel<<<(5 * 16384 + 255) / 256, 256>>>(W1, W2, W3, P1, P2, Whi, Wlo);
    scan1_kernel<<<nScanBlk, 1024>>>(deg, rowptr, bsum, N);
    scan2_kernel<<<1, 32>>>(bsum, nScanBlk);
    scan3_kernel<<<nScanBlk, 1024>>>(deg, rowptr, cur, bsum, N);
    fill_csr_kernel<<<(E + 255) / 256, 256>>>(src, dst, E, cur, eidx);

    int tilesN  = (N + 127) / 128;
    int tilesNE = (NE + 127) / 128;
    int gN  = tilesN  < 148 ? tilesN  : 148;
    int gNE = tilesNE < 148 ? tilesNE : 148;
    int aggBlk = (N * 32 + 255) / 256;

    // ---- GCN trunk ----
    gemm_mma_kernel<<<gN, 256, SMEM_BYTES>>>(x, nullptr, Whi, Wlo, nullptr, bufA,
                                             nullptr, nullptr, nullptr, N, 0, tilesN, 0);
    agg_kernel<<<aggBlk, 256>>>(bufA, rowptr, eidx, b1, bufB, 1, N);
    gemm_mma_kernel<<<gN, 256, SMEM_BYTES>>>(bufB, nullptr, Whi + 16384, Wlo + 16384, nullptr, bufA,
                                             nullptr, nullptr, nullptr, N, 0, tilesN, 0);
    agg_kernel<<<aggBlk, 256>>>(bufA, rowptr, eidx, b2, bufB, 1, N);
    gemm_mma_kernel<<<gN, 256, SMEM_BYTES>>>(bufB, nullptr, Whi + 2 * 16384, Wlo + 2 * 16384, nullptr, bufA,
                                             nullptr, nullptr, nullptr, N, 0, tilesN, 0);
    agg_kernel<<<aggBlk, 256>>>(bufA, rowptr, eidx, b3, bufB, 0, N);   // emb -> bufB

    // ---- link predictor ----
    // P1: gather-staging GEMM, A rows = emb[src]*emb[dst]
    gemm_mma_kernel<<<gNE, 256, SMEM_BYTES>>>(bufB, tedg, Whi + 3 * 16384, Wlo + 3 * 16384, pb1, Z2,
                                              nullptr, nullptr, nullptr, NE, 1, tilesNE, 1);
    // P2: fused final epilogue (z@P3 + normalize + log_softmax -> out)
    gemm_mma_kernel<<<gNE, 256, SMEM_BYTES>>>(Z2, nullptr, Whi + 4 * 16384, Wlo + 4 * 16384, pb2, nullptr,
                                              P3, pb3, out, NE, 1, tilesNE, 2);
}